// round 2
// baseline (speedup 1.0000x reference)
#include <cuda_runtime.h>

#define NE   1024
#define NIN  64
#define HID  128
#define NOUT 64

// Scratch (allocation-free rule: __device__ globals)
__device__ float g_A[NE * HID];
__device__ float g_B[NE * HID];
__device__ float g_S[NE * HID];

__device__ __forceinline__ float tanh_fast(float x) {
    float y;
    asm("tanh.approx.f32 %0, %1;" : "=f"(y) : "f"(x));
    return y;
}

// ---------------------------------------------------------------------------
// Kernel 1: A[i] = x[i] @ W1[0:64]  + b1 ;  B[i] = x[i] @ W1[64:128]
// Block: 128 threads (one per hidden h), PREP_IT rows of x per block.
// ---------------------------------------------------------------------------
#define PREP_IT 8
__global__ void prep_kernel(const float* __restrict__ x,
                            const float* __restrict__ W1,
                            const float* __restrict__ b1) {
    __shared__ float xs[PREP_IT][NIN];
    const int h  = threadIdx.x;
    const int i0 = blockIdx.x * PREP_IT;

    for (int t = h; t < PREP_IT * NIN; t += blockDim.x)
        xs[t / NIN][t % NIN] = x[i0 * NIN + t];
    __syncthreads();

    float a[PREP_IT], b[PREP_IT];
    const float bb1 = b1[h];
#pragma unroll
    for (int t = 0; t < PREP_IT; t++) { a[t] = bb1; b[t] = 0.f; }

#pragma unroll 8
    for (int k = 0; k < NIN; k++) {
        const float w1a = W1[k * HID + h];
        const float w1b = W1[(NIN + k) * HID + h];
#pragma unroll
        for (int t = 0; t < PREP_IT; t++) {
            a[t] += xs[t][k] * w1a;
            b[t] += xs[t][k] * w1b;
        }
    }
#pragma unroll
    for (int t = 0; t < PREP_IT; t++) {
        g_A[(i0 + t) * HID + h] = a[t];
        g_B[(i0 + t) * HID + h] = b[t];
    }
}

// ---------------------------------------------------------------------------
// Kernel 2 (hot): S[i][h] = sum_{p != i} tanh(A[i][h] + B[p][h])
// Block: 128 threads (one per h), IT i-rows per thread -> B reused 4x/load.
// MUFU.TANH-bound: 134M tanh / 2368 per-cyc ~ 57K cycles.
// ---------------------------------------------------------------------------
#define IT 4
__global__ void main_kernel() {
    const int h  = threadIdx.x;           // 0..127
    const int i0 = blockIdx.x * IT;

    float a[IT], acc[IT];
#pragma unroll
    for (int t = 0; t < IT; t++) {
        a[t]   = g_A[(i0 + t) * HID + h];
        acc[t] = 0.f;
    }

    const float* __restrict__ Bp = g_B + h;
#pragma unroll 8
    for (int p = 0; p < NE; p++) {
        const float b = __ldg(Bp + p * HID);
#pragma unroll
        for (int t = 0; t < IT; t++)
            acc[t] += tanh_fast(a[t] + b);
    }

    // remove the diagonal term p == i
#pragma unroll
    for (int t = 0; t < IT; t++) {
        const float bd = g_B[(i0 + t) * HID + h];
        acc[t] -= tanh_fast(a[t] + bd);
        g_S[(i0 + t) * HID + h] = acc[t];
    }
}

// ---------------------------------------------------------------------------
// Kernel 3: out[i] = b2 + (S[i] / 1023) @ W2
// Block: 64 threads (one per output o), FT i-rows per block.
// ---------------------------------------------------------------------------
#define FT 4
__global__ void fin_kernel(const float* __restrict__ W2,
                           const float* __restrict__ b2,
                           float* __restrict__ out) {
    __shared__ float ss[FT][HID];
    const int o  = threadIdx.x;   // 0..63
    const int i0 = blockIdx.x * FT;

    for (int t = o; t < FT * HID; t += blockDim.x)
        ss[t / HID][t % HID] = g_S[i0 * HID + t];
    __syncthreads();

    float acc[FT];
#pragma unroll
    for (int t = 0; t < FT; t++) acc[t] = 0.f;

#pragma unroll 8
    for (int hh = 0; hh < HID; hh++) {
        const float w = W2[hh * NOUT + o];
#pragma unroll
        for (int t = 0; t < FT; t++)
            acc[t] += ss[t][hh] * w;
    }

    const float bo  = b2[o];
    const float inv = 1.0f / (float)(NE - 1);
#pragma unroll
    for (int t = 0; t < FT; t++)
        out[(i0 + t) * NOUT + o] = bo + acc[t] * inv;
}

// ---------------------------------------------------------------------------
extern "C" void kernel_launch(void* const* d_in, const int* in_sizes, int n_in,
                              void* d_out, int out_size) {
    const float* x  = (const float*)d_in[0];
    const float* W1 = (const float*)d_in[1];
    const float* b1 = (const float*)d_in[2];
    const float* W2 = (const float*)d_in[3];
    const float* b2 = (const float*)d_in[4];
    float* out = (float*)d_out;

    prep_kernel<<<NE / PREP_IT, HID>>>(x, W1, b1);
    main_kernel<<<NE / IT, HID>>>();
    fin_kernel<<<NE / FT, NOUT>>>(W2, b2, out);
}

// round 4
// speedup vs baseline: 1.3204x; 1.3204x over previous
#include <cuda_runtime.h>

#define NE    1024
#define NIN   64
#define HID   128
#define NOUT  64

#define RIT   8              // rows per main block
#define PCH   128            // partners per main block
#define NPART (NE / PCH)     // 8 partner chunks

// Scratch (allocation-free rule: __device__ globals)
__device__ float g_A[NE * HID];
__device__ float g_B[NE * HID];
__device__ float g_P[NPART * NE * HID];   // 4 MB of partial sums

__device__ __forceinline__ float tanh_fast(float x) {
    float y;
    asm("tanh.approx.f32 %0, %1;" : "=f"(y) : "f"(x));
    return y;
}

// ---------------------------------------------------------------------------
// Kernel 1: A[i] = x[i] @ W1[0:64] + b1 ;  B[i] = x[i] @ W1[64:128]
// 256 blocks x 128 threads (thread = h), 4 rows per block.
// ---------------------------------------------------------------------------
#define PREP_IT 4
__global__ void prep_kernel(const float* __restrict__ x,
                            const float* __restrict__ W1,
                            const float* __restrict__ b1) {
    __shared__ float xs[PREP_IT][NIN];
    const int h  = threadIdx.x;
    const int i0 = blockIdx.x * PREP_IT;

    for (int t = h; t < PREP_IT * NIN; t += blockDim.x)
        xs[t / NIN][t % NIN] = x[i0 * NIN + t];
    __syncthreads();

    float a[PREP_IT], b[PREP_IT];
    const float bb1 = b1[h];
#pragma unroll
    for (int t = 0; t < PREP_IT; t++) { a[t] = bb1; b[t] = 0.f; }

#pragma unroll
    for (int k = 0; k < NIN; k++) {
        const float w1a = __ldg(&W1[k * HID + h]);
        const float w1b = __ldg(&W1[(NIN + k) * HID + h]);
#pragma unroll
        for (int t = 0; t < PREP_IT; t++) {
            a[t] += xs[t][k] * w1a;
            b[t] += xs[t][k] * w1b;
        }
    }
#pragma unroll
    for (int t = 0; t < PREP_IT; t++) {
        g_A[(i0 + t) * HID + h] = a[t];
        g_B[(i0 + t) * HID + h] = b[t];
    }
}

// ---------------------------------------------------------------------------
// Kernel 2 (hot): P[q][i][h] = sum_{p in chunk q} tanh(A[i][h] + B[p][h])
// 1024 blocks x 128 threads; block = (row-group r, partner-chunk q).
// MUFU.TANH roofline: 134M tanh / (148*4 SMSP * 4/cyc) ~ 57K cycles.
// ---------------------------------------------------------------------------
__global__ void main_kernel() {
    const int h  = threadIdx.x;                 // 0..127
    const int q  = blockIdx.x & (NPART - 1);    // partner chunk
    const int r  = blockIdx.x >> 3;             // row group (NPART==8)
    const int i0 = r * RIT;
    const int p0 = q * PCH;

    float a[RIT], acc[RIT];
#pragma unroll
    for (int t = 0; t < RIT; t++) {
        a[t]   = g_A[(i0 + t) * HID + h];
        acc[t] = 0.f;
    }

    const float* __restrict__ Bp = g_B + p0 * HID + h;
#pragma unroll 2
    for (int p = 0; p < PCH; p += 4) {
        const float b0 = __ldg(Bp + (p + 0) * HID);
        const float b1 = __ldg(Bp + (p + 1) * HID);
        const float b2 = __ldg(Bp + (p + 2) * HID);
        const float b3 = __ldg(Bp + (p + 3) * HID);
#pragma unroll
        for (int t = 0; t < RIT; t++) {
            acc[t] += tanh_fast(a[t] + b0);
            acc[t] += tanh_fast(a[t] + b1);
            acc[t] += tanh_fast(a[t] + b2);
            acc[t] += tanh_fast(a[t] + b3);
        }
    }

#pragma unroll
    for (int t = 0; t < RIT; t++)
        g_P[(q * NE + i0 + t) * HID + h] = acc[t];
}

// ---------------------------------------------------------------------------
// Kernel 3: out[i] = b2 + ((sum_q P[q][i] - tanh(A[i]+B[i])) / 1023) @ W2
// 128 blocks x 128 threads, 8 rows per block. All threads used in both stages.
// ---------------------------------------------------------------------------
#define FT 8
__global__ void fin_kernel(const float* __restrict__ W2,
                           const float* __restrict__ b2,
                           float* __restrict__ out) {
    __shared__ float ss[FT][HID];
    const int tid = threadIdx.x;
    const int i0  = blockIdx.x * FT;

    // stage 1: reduce partials + diagonal correction (thread = h)
    const int h = tid;
#pragma unroll
    for (int t = 0; t < FT; t++) {
        const int i = i0 + t;
        float s = 0.f;
#pragma unroll
        for (int qq = 0; qq < NPART; qq++)
            s += g_P[(qq * NE + i) * HID + h];
        s -= tanh_fast(g_A[i * HID + h] + g_B[i * HID + h]);
        ss[t][h] = s;
    }
    __syncthreads();

    // stage 2: dot with W2 (thread = (o, half-of-rows))
    const int o    = tid & (NOUT - 1);
    const int half = tid >> 6;                  // 0 or 1
    const float bo  = b2[o];
    const float inv = 1.0f / (float)(NE - 1);

#pragma unroll
    for (int t = half * (FT / 2); t < half * (FT / 2) + FT / 2; t++) {
        float acc = 0.f;
#pragma unroll 8
        for (int hh = 0; hh < HID; hh++)
            acc += ss[t][hh] * __ldg(&W2[hh * NOUT + o]);
        out[(i0 + t) * NOUT + o] = bo + acc * inv;
    }
}

// ---------------------------------------------------------------------------
extern "C" void kernel_launch(void* const* d_in, const int* in_sizes, int n_in,
                              void* d_out, int out_size) {
    const float* x  = (const float*)d_in[0];
    const float* W1 = (const float*)d_in[1];
    const float* b1 = (const float*)d_in[2];
    const float* W2 = (const float*)d_in[3];
    const float* b2 = (const float*)d_in[4];
    float* out = (float*)d_out;

    prep_kernel<<<NE / PREP_IT, HID>>>(x, W1, b1);
    main_kernel<<<(NE / RIT) * NPART, HID>>>();
    fin_kernel<<<NE / FT, HID>>>(W2, b2, out);
}